// round 3
// baseline (speedup 1.0000x reference)
#include <cuda_runtime.h>
#include <math.h>

// ---------------- problem constants ----------------
#define T_   32
#define B_   32
#define H_   128
#define W_   128
#define CIN_ 2
#define FH_  32
#define FW_  32
#define CF_  64
#define CP_  32
#define OUT_ 128
#define PH_  16
#define PW_  16
// periph resized size
#define RH_  64
#define RW_  64

// output layout offsets (floats)
// out:      [0, 4096)              (B, OUT)
// logits:   [4096, 135168)         (T, B, OUT)
// sr:       [135168, 135170)
// active:   [135170]
// route:    [135171, 135427)       (256)
// chan:     [135427, 135491)       (64)
#define OFF_LOGITS 4096
#define OFF_SR     135168
#define OFF_ACTIVE 135170
#define OFF_ROUTE  135171
#define OFF_CHAN   135427

// ---------------- persistent device state ----------------
__device__ float g_vf[B_ * FH_ * FW_ * CF_];     // 8 MB
__device__ float g_vp[B_ * RH_ * RW_ * CP_];     // 16 MB
__device__ float g_ff[B_ * FH_ * FW_ * CF_];     // 8 MB scratch (per step)
__device__ float g_scores[B_ * 256];
__device__ float g_sal[B_ * CF_];
__device__ float g_fused[B_ * 96];
__device__ int   g_y0[B_], g_x0[B_];
__device__ int   g_sr0, g_sr1, g_active;
__device__ int   g_route[256];
__device__ int   g_chan[CF_];

// ---------------- init ----------------
__global__ void k_init() {
    int i = blockIdx.x * blockDim.x + threadIdx.x;
    int stride = gridDim.x * blockDim.x;
    for (int j = i; j < B_ * FH_ * FW_ * CF_; j += stride) g_vf[j] = 0.f;
    for (int j = i; j < B_ * RH_ * RW_ * CP_; j += stride) g_vp[j] = 0.f;
    if (i < 256) g_route[i] = 0;
    if (i < 64)  g_chan[i]  = 0;
    if (i == 0) { g_sr0 = 0; g_sr1 = 0; g_active = 0; }
}

// ---------------- kernel A: scores, argmax, region gate, active, fovea coords ----------------
// grid: B blocks, 256 threads (one thread per 8x8 patch)
__global__ void k_A(const float* __restrict__ x_seq, int t) {
    int b = blockIdx.x, tid = threadIdx.x;
    const float* x = x_seq + ((size_t)(t * B_ + b)) * H_ * W_ * CIN_;

    __shared__ float s_sc[256];
    __shared__ float s_thresh;
    __shared__ unsigned long long s_key[256];
    __shared__ int s_cnt[256];

    int py = tid >> 4, px = tid & 15;
    float sum = 0.f; int cnt = 0;
    for (int r = 0; r < 8; r++) {
        const float* row = x + ((py * 8 + r) * W_ + px * 8) * CIN_;
#pragma unroll
        for (int k = 0; k < 16; k++) {
            float v = row[k];
            float a = fabsf(v);
            if (a > 0.5f) { cnt++; sum += a; }
        }
    }
    float sc = sum * (1.f / 128.f);
    s_sc[tid] = sc;
    g_scores[b * 256 + tid] = sc;
    s_cnt[tid] = cnt;
    // argmax key: larger score wins; on tie, smaller patch index wins
    unsigned int fb = __float_as_uint(sc);   // sc >= 0, so bit pattern is order-preserving
    s_key[tid] = (((unsigned long long)fb) << 32) | (unsigned long long)(0xFFFFFFFFu - (unsigned)tid);
    __syncthreads();

    // exact top-4 threshold (JAX top_k semantics with ties)
    int cg = 0, ceq = 0;
    for (int j = 0; j < 256; j++) {
        float v = s_sc[j];
        cg  += (v > sc);
        ceq += (v == sc);
    }
    if (cg <= 3 && cg + ceq > 3) s_thresh = sc;

    // reduce active count + argmax key
    for (int off = 128; off > 0; off >>= 1) {
        __syncthreads();
        if (tid < off) {
            s_cnt[tid] += s_cnt[tid + off];
            if (s_key[tid + off] > s_key[tid]) s_key[tid] = s_key[tid + off];
        }
    }
    __syncthreads();

    float thr = s_thresh;
    if (sc >= thr) atomicAdd(&g_route[tid], 1);

    if (tid == 0) {
        atomicAdd(&g_active, s_cnt[0]);
        unsigned int low = (unsigned int)(s_key[0] & 0xFFFFFFFFull);
        int best = (int)(0xFFFFFFFFu - low);
        int cy = (best / PW_) * 8 + 4;
        int cx = (best % PW_) * 8 + 4;
        int y0 = cy - 16; y0 = y0 < 0 ? 0 : (y0 > H_ - FH_ ? H_ - FH_ : y0);
        int x0 = cx - 16; x0 = x0 < 0 ? 0 : (x0 > W_ - FW_ ? W_ - FW_ : x0);
        g_y0[b] = y0; g_x0[b] = x0;
    }
    // per-step zeroing of accumulators owned by this batch
    if (tid < 64) g_sal[b * 64 + tid] = 0.f;
    if (tid < 96) g_fused[b * 96 + tid] = 0.f;
}

// ---------------- kernel B1: fovea conv -> g_ff, saliency partials ----------------
// grid: (8, B) blocks (4-row tiles), 256 threads: co = tid&63, row-in-tile q = tid>>6
__global__ void k_B1(const float* __restrict__ x_seq, const float* __restrict__ w_fovea, int t) {
    int ry = blockIdx.x;   // 0..7
    int b  = blockIdx.y;
    int tid = threadIdx.x;

    __shared__ float s_in[6 * 32 * 2];   // rows ry*4-1 .. ry*4+4, [r][col][c]
    __shared__ float s_w[3 * 3 * 2 * 64];
    __shared__ float s_part[256];

    int y0 = g_y0[b], x0 = g_x0[b];
    const float* x = x_seq + ((size_t)(t * B_ + b)) * H_ * W_ * CIN_;

    for (int idx = tid; idx < 384; idx += 256) {
        int r = idx >> 6;         // 0..5
        int rest = idx & 63;      // col*2 + c
        int lrow = ry * 4 - 1 + r;
        float v = 0.f;
        if (lrow >= 0 && lrow < 32) {
            float xv = x[(size_t)(y0 + lrow) * (W_ * CIN_) + x0 * CIN_ + rest];
            v = (fabsf(xv) > 0.5f) ? xv : 0.f;
        }
        s_in[idx] = v;
    }
    for (int idx = tid; idx < 1152; idx += 256) s_w[idx] = w_fovea[idx];
    __syncthreads();

    int co = tid & 63, q = tid >> 6;     // q = local row 0..3
    int row = ry * 4 + q;
    float asum = 0.f;
    float* ffout = &g_ff[(((size_t)(b * 32 + row)) * 32) * 64 + co];
    for (int j = 0; j < 32; j++) {
        float acc = 0.f;
#pragma unroll
        for (int di = 0; di < 3; di++) {
            const float* inr = &s_in[(q + di) * 64];
#pragma unroll
            for (int dj = 0; dj < 3; dj++) {
                int jc = j + dj - 1;
                if (jc >= 0 && jc < 32) {
                    const float* wp = &s_w[((di * 3 + dj) * 2) * 64 + co];
                    acc += inr[jc * 2 + 0] * wp[0];
                    acc += inr[jc * 2 + 1] * wp[64];
                }
            }
        }
        ffout[(size_t)j * 64] = acc;
        asum += fabsf(acc);
    }
    s_part[tid] = asum;
    __syncthreads();
    if (tid < 64) {
        float tot = s_part[tid] + s_part[tid + 64] + s_part[tid + 128] + s_part[tid + 192];
        atomicAdd(&g_sal[b * 64 + tid], tot);
    }
}

// ---------------- kernel BC: fovea gate+LIF (bx<8) | periph resize+conv+LIF (bx>=8) ----------------
// grid: (16, B), 256 threads
__global__ void k_BC(const float* __restrict__ x_seq, const float* __restrict__ w_periph, int t) {
    int bx = blockIdx.x;
    int b  = blockIdx.y;
    int tid = threadIdx.x;

    __shared__ float smem[10816];

    if (bx < 8) {
        // ---- fovea apply: KWTA gate, vf update, spikes ----
        float* s_sal  = smem;          // 64
        float* s_gate = smem + 64;     // 64
        float* s_thr  = smem + 128;    // 1
        float* s_red  = smem + 192;    // 256
        int*   s_tot  = (int*)(smem + 448);

        if (tid < 64) s_sal[tid] = g_sal[b * 64 + tid];
        if (tid == 0) *s_tot = 0;
        __syncthreads();
        if (tid < 64) {
            float v = s_sal[tid];
            int cg = 0, ceq = 0;
            for (int j = 0; j < 64; j++) {
                float u = s_sal[j];
                cg  += (u > v);
                ceq += (u == v);
            }
            if (cg <= 15 && cg + ceq > 15) *s_thr = v;
        }
        __syncthreads();
        if (tid < 64) {
            float g = (s_sal[tid] >= *s_thr) ? 1.f : 0.f;
            s_gate[tid] = g;
            if (bx == 0 && g > 0.f) atomicAdd(&g_chan[tid], 1);
        }
        __syncthreads();

        int co = tid & 63;
        float gate = s_gate[co];
        size_t base = (size_t)b * 65536 + (size_t)bx * 8192;   // 4 rows * 32 * 64
        int cnt = 0;
#pragma unroll 4
        for (int k = 0; k < 32; k++) {
            size_t idx = base + (size_t)k * 256 + tid;
            float ffv = g_ff[idx] * gate;
            float v = 0.9f * g_vf[idx] + ffv;
            float s = (v - 1.0f > 0.f) ? 1.f : 0.f;
            v -= s;
            g_vf[idx] = v;
            cnt += (s > 0.f);
        }
        s_red[tid] = (float)cnt;
        __syncthreads();
        if (tid < 64) {
            float chc = s_red[tid] + s_red[tid + 64] + s_red[tid + 128] + s_red[tid + 192];
            atomicAdd(&g_fused[b * 96 + tid], chc * (1.f / 1024.f));
            atomicAdd(s_tot, (int)chc);
        }
        __syncthreads();
        if (tid == 0) atomicAdd(&g_sr0, *s_tot);
    } else {
        // ---- periph: resize (exact JAX antialias-linear 2x down) + conv + vp LIF ----
        int rt = bx - 8;   // 0..7, output rows [rt*8, rt*8+8)
        float* s_w   = smem;                          // 576
        float* s_xin = smem + 576;                    // 22*256 = 5632
        float* s_h   = smem + 576 + 5632;             // 22*128 = 2816
        float* s_rz  = smem + 576 + 5632 + 2816;      // 10*128 = 1280
        float* s_red = smem + 576 + 5632 + 2816 + 1280; // 256
        int*   s_tot = (int*)(s_red + 256);

        const float* x = x_seq + ((size_t)(t * B_ + b)) * H_ * W_ * CIN_;
        for (int idx = tid; idx < 576; idx += 256) s_w[idx] = w_periph[idx];
        if (tid == 0) *s_tot = 0;

        int r0 = 16 * rt - 3;
        for (int idx = tid; idx < 5632; idx += 256) {
            int r = idx >> 8;       // input row offset 0..21
            int c = idx & 255;      // col*2 + ch
            int gr = r0 + r;
            float v = 0.f;
            if (gr >= 0 && gr < H_) {
                float xv = x[(size_t)gr * 256 + c];
                v = (fabsf(xv) > 0.5f) ? xv : 0.f;
            }
            s_xin[idx] = v;
        }
        __syncthreads();

        // horizontal resize: 22 rows x 64 x 2
        for (int idx = tid; idx < 2816; idx += 256) {
            int r = idx >> 7;
            int rest = idx & 127;   // ox*2 + c
            int ox = rest >> 1;
            int c = rest & 1;
            int kb; float w0, w1, w2, w3;
            if (ox == 0)       { kb = -1;  w0 = 0.f;       w1 = 3.f / 7.f; w2 = 3.f / 7.f; w3 = 1.f / 7.f; }
            else if (ox == 63) { kb = 125; w0 = 1.f / 7.f; w1 = 3.f / 7.f; w2 = 3.f / 7.f; w3 = 0.f; }
            else               { kb = 2 * ox - 1; w0 = 0.125f; w1 = 0.375f; w2 = 0.375f; w3 = 0.125f; }
            const float* xr = &s_xin[r * 256];
            int k0 = kb < 0 ? 0 : kb;
            int k3 = (kb + 3) > 127 ? 127 : (kb + 3);
            float v = w0 * xr[k0 * 2 + c] + w1 * xr[(kb + 1) * 2 + c]
                    + w2 * xr[(kb + 2) * 2 + c] + w3 * xr[k3 * 2 + c];
            s_h[idx] = v;
        }
        __syncthreads();

        // vertical resize: rows rt*8-1 .. rt*8+8 (zero pad outside [0,64))
        for (int idx = tid; idx < 1280; idx += 256) {
            int lr = idx >> 7;
            int rest = idx & 127;
            int oy = rt * 8 - 1 + lr;
            float v = 0.f;
            if (oy >= 0 && oy < 64) {
                int jb; float w0, w1, w2, w3;
                if (oy == 0)       { jb = -1;  w0 = 0.f;       w1 = 3.f / 7.f; w2 = 3.f / 7.f; w3 = 1.f / 7.f; }
                else if (oy == 63) { jb = 125; w0 = 1.f / 7.f; w1 = 3.f / 7.f; w2 = 3.f / 7.f; w3 = 0.f; }
                else               { jb = 2 * oy - 1; w0 = 0.125f; w1 = 0.375f; w2 = 0.375f; w3 = 0.125f; }
                int base = jb - r0;
                v = w0 * s_h[(base + 0) * 128 + rest] + w1 * s_h[(base + 1) * 128 + rest]
                  + w2 * s_h[(base + 2) * 128 + rest] + w3 * s_h[(base + 3) * 128 + rest];
            }
            s_rz[idx] = v;
        }
        __syncthreads();

        // conv 3x3x2 -> 32 + vp LIF
        int co = tid & 31, g = tid >> 5;   // g = local output row 0..7
        int oy = rt * 8 + g;
        int cnt = 0;
        for (int ox = 0; ox < 64; ox++) {
            float acc = 0.f;
#pragma unroll
            for (int di = 0; di < 3; di++) {
                const float* rz = &s_rz[(g + di) * 128];
#pragma unroll
                for (int dj = 0; dj < 3; dj++) {
                    int xc = ox + dj - 1;
                    if (xc >= 0 && xc < 64) {
                        const float* wp = &s_w[((di * 3 + dj) * 2) * 32 + co];
                        acc += rz[xc * 2 + 0] * wp[0];
                        acc += rz[xc * 2 + 1] * wp[32];
                    }
                }
            }
            size_t idx = (((size_t)(b * 64 + oy)) * 64 + ox) * 32 + co;
            float v = 0.9f * g_vp[idx] + acc;
            float s = (v - 1.0f > 0.f) ? 1.f : 0.f;
            v -= s;
            g_vp[idx] = v;
            cnt += (s > 0.f);
        }
        s_red[tid] = (float)cnt;
        __syncthreads();
        if (tid < 32) {
            float chc = 0.f;
#pragma unroll
            for (int g2 = 0; g2 < 8; g2++) chc += s_red[g2 * 32 + tid];
            atomicAdd(&g_fused[b * 96 + 64 + tid], chc * (1.f / 4096.f));
            atomicAdd(s_tot, (int)chc);
        }
        __syncthreads();
        if (tid == 0) atomicAdd(&g_sr1, *s_tot);
    }
}

// ---------------- kernel D: logits ----------------
// grid: B blocks, 128 threads
__global__ void k_D(const float* __restrict__ head_w, const float* __restrict__ head_b,
                    const float* __restrict__ route_w, const float* __restrict__ route_b,
                    float* __restrict__ out, int t) {
    int b = blockIdx.x, o = threadIdx.x;
    __shared__ float s_f[96];
    __shared__ float s_s[256];
    if (o < 96) s_f[o] = g_fused[b * 96 + o];
    for (int k = o; k < 256; k += 128) s_s[k] = g_scores[b * 256 + k];
    __syncthreads();
    float acc = head_b[o] + route_b[o];
    for (int c = 0; c < 96; c++)  acc += s_f[c] * head_w[c * 128 + o];
    for (int k = 0; k < 256; k++) acc += s_s[k] * route_w[k * 128 + o];
    out[OFF_LOGITS + ((size_t)(t * B_ + b)) * 128 + o] = acc;
}

// ---------------- kernel F: final mean over T + stats ----------------
// grid: 33 blocks, 128 threads
__global__ void k_F(float* __restrict__ out) {
    int bid = blockIdx.x, tid = threadIdx.x;
    if (bid < 32) {
        float acc = 0.f;
        for (int t = 0; t < 32; t++)
            acc += out[OFF_LOGITS + ((size_t)(t * 32 + bid)) * 128 + tid];
        out[bid * 128 + tid] = acc * (1.f / 32.f);
    } else {
        for (int k = tid; k < 256; k += 128)
            out[OFF_ROUTE + k] = (float)g_route[k] * (1.f / 1024.f);
        if (tid < 64)
            out[OFF_CHAN + tid] = (float)g_chan[tid] * (1.f / 1024.f);
        if (tid == 0) {
            out[OFF_SR + 0]  = (float)g_sr0 * (1.f / 67108864.f);    // T*B*32*32*64
            out[OFF_SR + 1]  = (float)g_sr1 * (1.f / 134217728.f);   // T*B*64*64*32
            out[OFF_ACTIVE]  = (float)g_active * (1.f / 33554432.f); // T*B*128*128*2
        }
    }
}

// ---------------- launch ----------------
extern "C" void kernel_launch(void* const* d_in, const int* in_sizes, int n_in,
                              void* d_out, int out_size) {
    const float* x_seq   = (const float*)d_in[0];
    const float* w_fovea = (const float*)d_in[1];
    const float* w_periph= (const float*)d_in[2];
    const float* head_w  = (const float*)d_in[3];
    const float* head_b  = (const float*)d_in[4];
    const float* route_w = (const float*)d_in[5];
    const float* route_b = (const float*)d_in[6];
    float* out = (float*)d_out;

    k_init<<<512, 256>>>();
    for (int t = 0; t < T_; t++) {
        k_A<<<B_, 256>>>(x_seq, t);
        k_B1<<<dim3(8, B_), 256>>>(x_seq, w_fovea, t);
        k_BC<<<dim3(16, B_), 256>>>(x_seq, w_periph, t);
        k_D<<<B_, 128>>>(head_w, head_b, route_w, route_b, out, t);
    }
    k_F<<<33, 128>>>(out);
}

// round 7
// speedup vs baseline: 4.2318x; 4.2318x over previous
#include <cuda_runtime.h>
#include <math.h>

#define T_   32
#define B_   32
#define H_   128
#define W_   128

// output layout offsets (floats)
#define OFF_LOGITS 4096
#define OFF_SR     135168
#define OFF_ACTIVE 135170
#define OFF_ROUTE  135171
#define OFF_CHAN   135427

// ---------------- persistent device state ----------------
__device__ float g_scores[T_ * B_ * 256];
__device__ __align__(16) float g_gate[T_ * B_ * 64];   // float2-loaded -> force 16B alignment
__device__ int   g_y0[T_ * B_], g_x0[T_ * B_];
__device__ int   g_fcnt[T_ * B_ * 96];     // spike counts per (t,b,channel): 64 fovea + 32 periph
__device__ int   g_route[256];
__device__ int   g_chan[64];
__device__ int   g_active;

// packed fp32x2 FMA (Blackwell FFMA2) — bit-exact IEEE fp32 per lane
__device__ __forceinline__ float2 ffma2(float a, float2 w, float2 c) {
#if __CUDA_ARCH__ >= 1000
    union { float2 f; unsigned long long u; } A, W, C, R;
    A.f = make_float2(a, a); W.f = w; C.f = c;
    asm("fma.rn.f32x2 %0, %1, %2, %3;" : "=l"(R.u) : "l"(A.u), "l"(W.u), "l"(C.u));
    return R.f;
#else
    return make_float2(fmaf(a, w.x, c.x), fmaf(a, w.y, c.y));
#endif
}

// 6 taps of one conv row (3 x-positions x 2 input channels), channel-pair packed.
// Accumulation order per channel: dj = 0,1,2 with ci = 0,1 inner (matches scalar version).
#define CONV_ROW(rp, wrow, acc) do {                       \
    float2 _i0 = ((const float2*)(rp))[0];                 \
    float2 _i1 = ((const float2*)(rp))[1];                 \
    float2 _i2 = ((const float2*)(rp))[2];                 \
    acc = ffma2(_i0.x, (wrow)[0][0], acc);                 \
    acc = ffma2(_i0.y, (wrow)[0][1], acc);                 \
    acc = ffma2(_i1.x, (wrow)[1][0], acc);                 \
    acc = ffma2(_i1.y, (wrow)[1][1], acc);                 \
    acc = ffma2(_i2.x, (wrow)[2][0], acc);                 \
    acc = ffma2(_i2.y, (wrow)[2][1], acc);                 \
} while (0)

// ---------------- init ----------------
__global__ void k_init() {
    int i = blockIdx.x * blockDim.x + threadIdx.x;
    int stride = gridDim.x * blockDim.x;
    for (int j = i; j < T_ * B_ * 96; j += stride) g_fcnt[j] = 0;
    if (i < 256) g_route[i] = 0;
    if (i < 64)  g_chan[i]  = 0;
    if (i == 0)  g_active   = 0;
}

// ---------------- k_pre: per (t,b): scores/argmax/route/active + fovea conv -> sal -> gate ----
// grid: T*B = 1024 blocks, 256 threads
__global__ void __launch_bounds__(256, 4)
k_pre(const float* __restrict__ x_seq, const float* __restrict__ w_fovea) {
    int idx = blockIdx.x;
    int b = idx & 31, t = idx >> 5;
    int tb = t * 32 + b;
    int tid = threadIdx.x;
    const float* x = x_seq + (size_t)tb * 32768;

    __shared__ float s_sc[256];
    __shared__ unsigned long long s_key[256];
    __shared__ int   s_acnt[256];
    __shared__ float s_thresh;
    __shared__ int   s_y0, s_x0;
    __shared__ __align__(16) float s_win[34 * 68];   // zero-padded fovea window; float2-read
    __shared__ float s_asum[8 * 64];
    __shared__ float s_sal[64];
    __shared__ float s_thr2;

    // ---- part 1: patch scores (one thread per 8x8 patch; identical arithmetic order) ----
    int py = tid >> 4, px = tid & 15;
    float sum = 0.f; int cnt = 0;
    for (int r = 0; r < 8; r++) {
        const float* row = x + ((py * 8 + r) * W_ + px * 8) * 2;
#pragma unroll
        for (int k = 0; k < 16; k++) {
            float v = row[k];
            float a = fabsf(v);
            if (a > 0.5f) { cnt++; sum += a; }
        }
    }
    float sc = sum * (1.f / 128.f);
    s_sc[tid] = sc;
    g_scores[tb * 256 + tid] = sc;
    s_acnt[tid] = cnt;
    unsigned int fb = __float_as_uint(sc);   // sc >= 0 -> order-preserving
    s_key[tid] = (((unsigned long long)fb) << 32) | (unsigned long long)(0xFFFFFFFFu - (unsigned)tid);
    __syncthreads();

    // exact top-4 threshold (JAX top_k tie semantics)
    int cg = 0, ceq = 0;
    for (int j = 0; j < 256; j++) {
        float v = s_sc[j];
        cg  += (v > sc);
        ceq += (v == sc);
    }
    if (cg <= 3 && cg + ceq > 3) s_thresh = sc;

    for (int off = 128; off > 0; off >>= 1) {
        __syncthreads();
        if (tid < off) {
            s_acnt[tid] += s_acnt[tid + off];
            if (s_key[tid + off] > s_key[tid]) s_key[tid] = s_key[tid + off];
        }
    }
    __syncthreads();

    if (sc >= s_thresh) atomicAdd(&g_route[tid], 1);
    if (tid == 0) {
        atomicAdd(&g_active, s_acnt[0]);
        unsigned int low = (unsigned int)(s_key[0] & 0xFFFFFFFFull);
        int best = (int)(0xFFFFFFFFu - low);
        int cy = (best >> 4) * 8 + 4;
        int cx = (best & 15) * 8 + 4;
        int y0 = cy - 16; y0 = y0 < 0 ? 0 : (y0 > 96 ? 96 : y0);
        int x0 = cx - 16; x0 = x0 < 0 ? 0 : (x0 > 96 ? 96 : x0);
        s_y0 = y0; s_x0 = x0;
        g_y0[tb] = y0; g_x0[tb] = x0;
    }

    // ---- part 2: fovea window load (event-masked, zero-padded) ----
    for (int i = tid; i < 34 * 68; i += 256) s_win[i] = 0.f;
    __syncthreads();
    int y0 = s_y0, x0 = s_x0;
    for (int i = tid; i < 2048; i += 256) {
        int rr = i >> 6, col = i & 63;
        float xv = x[(size_t)(y0 + rr) * 256 + x0 * 2 + col];
        s_win[(rr + 1) * 68 + col + 2] = (fabsf(xv) > 0.5f) ? xv : 0.f;
    }
    __syncthreads();

    // ---- part 3: conv -> per-channel |ff| sums -> KWTA gate ----
    int p = tid & 31;           // channel pair
    int g = tid >> 5;           // row group (4 rows each)
    float2 w2[3][3][2];
#pragma unroll
    for (int di = 0; di < 3; di++)
#pragma unroll
        for (int dj = 0; dj < 3; dj++)
#pragma unroll
            for (int ci = 0; ci < 2; ci++)
                w2[di][dj][ci] = *(const float2*)&w_fovea[((di * 3 + dj) * 2 + ci) * 64 + 2 * p];

    float2 asum = make_float2(0.f, 0.f);
    for (int rq = 0; rq < 4; rq++) {
        int row = g * 4 + rq;
#pragma unroll 4
        for (int j = 0; j < 32; j++) {
            float2 acc = make_float2(0.f, 0.f);
#pragma unroll
            for (int di = 0; di < 3; di++) {
                const float* rp = &s_win[(row + di) * 68 + j * 2];
                CONV_ROW(rp, w2[di], acc);
            }
            asum.x += fabsf(acc.x);
            asum.y += fabsf(acc.y);
        }
    }
    s_asum[g * 64 + 2 * p]     = asum.x;
    s_asum[g * 64 + 2 * p + 1] = asum.y;
    __syncthreads();
    if (tid < 64) {
        float s = 0.f;
#pragma unroll
        for (int gg = 0; gg < 8; gg++) s += s_asum[gg * 64 + tid];
        s_sal[tid] = s;
    }
    __syncthreads();
    if (tid < 64) {
        float vv = s_sal[tid];
        int cg2 = 0, ce2 = 0;
        for (int j = 0; j < 64; j++) {
            float u = s_sal[j];
            cg2 += (u > vv);
            ce2 += (u == vv);
        }
        if (cg2 <= 15 && cg2 + ce2 > 15) s_thr2 = vv;
    }
    __syncthreads();
    if (tid < 64) {
        float gt = (s_sal[tid] >= s_thr2) ? 1.f : 0.f;
        g_gate[tb * 64 + tid] = gt;
        if (gt > 0.f) atomicAdd(&g_chan[tid], 1);
    }
}

// ---------------- k_lif: all 32 timesteps in registers ----------------
// blocks [0,256): fovea   — b = bx>>3, row tile = bx&7 (4 rows)
// blocks [256,768): periph — b = (bx-256)>>4, row tile = (bx-256)&15 (4 output rows)
__global__ void __launch_bounds__(256, 2)
k_lif(const float* __restrict__ x_seq,
      const float* __restrict__ w_fovea,
      const float* __restrict__ w_periph) {
    __shared__ __align__(16) float sbuf[7248];
    int bx = blockIdx.x;
    int tid = threadIdx.x;

    if (bx < 256) {
        // ================= fovea: conv recompute + gate + LIF =================
        int b = bx >> 3, tile = bx & 7;
        float* s_in  = sbuf;                 // [6][68] zero-padded cols (row = 272B, 16B-mult)
        int*   s_cnt = (int*)(sbuf + 416);   // [32][64]

        for (int i = tid; i < 408;  i += 256) s_in[i] = 0.f;
        for (int i = tid; i < 2048; i += 256) s_cnt[i] = 0;

        int p  = tid & 31;         // channel pair (warp-unique -> conflict-free)
        int q  = (tid >> 5) & 3;   // row within tile
        int xh = tid >> 7;         // x half (0/1)

        float2 w2[3][3][2];
#pragma unroll
        for (int di = 0; di < 3; di++)
#pragma unroll
            for (int dj = 0; dj < 3; dj++)
#pragma unroll
                for (int ci = 0; ci < 2; ci++)
                    w2[di][dj][ci] = *(const float2*)&w_fovea[((di * 3 + dj) * 2 + ci) * 64 + 2 * p];

        float2 v[16];
#pragma unroll
        for (int j = 0; j < 16; j++) v[j] = make_float2(0.f, 0.f);

        int r0 = tile * 4;
        __syncthreads();

        for (int t = 0; t < 32; t++) {
            int tb = t * 32 + b;
            int y0 = g_y0[tb], x0 = g_x0[tb];
            const float* x = x_seq + (size_t)tb * 32768;
            for (int i = tid; i < 384; i += 256) {
                int rr = i >> 6, col = i & 63;
                int lrow = r0 - 1 + rr;
                if (lrow >= 0 && lrow < 32) {
                    float xv = x[(size_t)(y0 + lrow) * 256 + x0 * 2 + col];
                    s_in[rr * 68 + col + 2] = (fabsf(xv) > 0.5f) ? xv : 0.f;
                }
            }
            float2 g2 = *(const float2*)&g_gate[tb * 64 + 2 * p];
            __syncthreads();

            int c0 = 0, c1 = 0;
#pragma unroll
            for (int j = 0; j < 16; j++) {
                int xx = xh * 16 + j;
                float2 acc = make_float2(0.f, 0.f);
#pragma unroll
                for (int di = 0; di < 3; di++) {
                    const float* rp = &s_in[(q + di) * 68 + xx * 2];
                    CONV_ROW(rp, w2[di], acc);
                }
                float vx = 0.9f * v[j].x + acc.x * g2.x;
                float vy = 0.9f * v[j].y + acc.y * g2.y;
                if (vx > 1.0f) { vx -= 1.0f; c0++; }
                if (vy > 1.0f) { vy -= 1.0f; c1++; }
                v[j].x = vx; v[j].y = vy;
            }
            atomicAdd(&s_cnt[t * 64 + 2 * p],     c0);
            atomicAdd(&s_cnt[t * 64 + 2 * p + 1], c1);
            __syncthreads();
        }
        for (int i = tid; i < 2048; i += 256) {
            int t = i >> 6, c = i & 63;
            int val = s_cnt[i];
            if (val) atomicAdd(&g_fcnt[(t * 32 + b) * 96 + c], val);
        }
    } else {
        // ================= periph: resize + conv + LIF, fully fused =================
        int pbx = bx - 256;
        int b = pbx >> 4, tile = pbx & 15;        // output rows [4*tile, 4*tile+4)
        float* s_x   = sbuf;                       // [14][260] zero-padded cols
        float* s_h   = sbuf + 3640;                // [14][128]
        float* s_rz  = sbuf + 3640 + 1792;         // [6][132] zero-padded cols (base 21728B, row 528B)
        int*   s_cnt = (int*)(sbuf + 3640 + 1792 + 792);  // [32][32]

        for (int i = tid; i < 3640; i += 256) s_x[i]  = 0.f;
        for (int i = tid; i < 792;  i += 256) s_rz[i] = 0.f;
        for (int i = tid; i < 1024; i += 256) s_cnt[i] = 0;

        int p  = tid & 15;   // channel pair
        int xg = tid >> 4;   // x group: x in [4*xg, 4*xg+4)

        float2 w2[3][3][2];
#pragma unroll
        for (int di = 0; di < 3; di++)
#pragma unroll
            for (int dj = 0; dj < 3; dj++)
#pragma unroll
                for (int ci = 0; ci < 2; ci++)
                    w2[di][dj][ci] = *(const float2*)&w_periph[((di * 3 + dj) * 2 + ci) * 32 + 2 * p];

        float2 v[4][4];
#pragma unroll
        for (int yo = 0; yo < 4; yo++)
#pragma unroll
            for (int j = 0; j < 4; j++) v[yo][j] = make_float2(0.f, 0.f);

        int ir0 = 8 * tile - 3;
        __syncthreads();

        for (int t = 0; t < 32; t++) {
            const float* x = x_seq + (size_t)(t * 32 + b) * 32768;
            // load 14 input rows, event-masked (OOB rows explicitly zero)
            for (int i = tid; i < 3584; i += 256) {
                int r = i >> 8, c = i & 255;
                int gr = ir0 + r;
                float vv = 0.f;
                if (gr >= 0 && gr < 128) {
                    float xv = x[(size_t)gr * 256 + c];
                    vv = (fabsf(xv) > 0.5f) ? xv : 0.f;
                }
                s_x[r * 260 + c + 2] = vv;
            }
            __syncthreads();
            // horizontal resize (exact JAX antialias-linear weights; OOB taps have zero weight)
            for (int i = tid; i < 1792; i += 256) {
                int r = i >> 7, rest = i & 127;
                int ox = rest >> 1, c = rest & 1;
                int kb; float w0, w1, wm, w3;
                if (ox == 0)       { kb = -1;  w0 = 0.f;       w1 = 3.f / 7.f; wm = 3.f / 7.f; w3 = 1.f / 7.f; }
                else if (ox == 63) { kb = 125; w0 = 1.f / 7.f; w1 = 3.f / 7.f; wm = 3.f / 7.f; w3 = 0.f; }
                else               { kb = 2 * ox - 1; w0 = 0.125f; w1 = 0.375f; wm = 0.375f; w3 = 0.125f; }
                const float* xr = &s_x[r * 260 + 2 + c];
                float vv = w0 * xr[kb * 2] + w1 * xr[(kb + 1) * 2]
                         + wm * xr[(kb + 2) * 2] + w3 * xr[(kb + 3) * 2];
                s_h[i] = vv;
            }
            __syncthreads();
            // vertical resize into zero-padded conv input rows oy = 4*tile-1 .. 4*tile+4
            for (int i = tid; i < 768; i += 256) {
                int lr = i >> 7, rest = i & 127;
                int oy = 4 * tile - 1 + lr;
                float vv = 0.f;
                if (oy >= 0 && oy < 64) {
                    int jb; float w0, w1, wm, w3;
                    if (oy == 0)       { jb = -1;  w0 = 0.f;       w1 = 3.f / 7.f; wm = 3.f / 7.f; w3 = 1.f / 7.f; }
                    else if (oy == 63) { jb = 125; w0 = 1.f / 7.f; w1 = 3.f / 7.f; wm = 3.f / 7.f; w3 = 0.f; }
                    else               { jb = 2 * oy - 1; w0 = 0.125f; w1 = 0.375f; wm = 0.375f; w3 = 0.125f; }
                    int base = jb - ir0;
                    vv = w0 * s_h[base * 128 + rest]       + w1 * s_h[(base + 1) * 128 + rest]
                       + wm * s_h[(base + 2) * 128 + rest] + w3 * s_h[(base + 3) * 128 + rest];
                }
                s_rz[lr * 132 + rest + 2] = vv;
            }
            __syncthreads();
            // conv 3x3x2 -> channel pair + LIF
            int c0 = 0, c1 = 0;
#pragma unroll
            for (int yo = 0; yo < 4; yo++) {
#pragma unroll
                for (int j = 0; j < 4; j++) {
                    int xx = 4 * xg + j;
                    float2 acc = make_float2(0.f, 0.f);
#pragma unroll
                    for (int di = 0; di < 3; di++) {
                        const float* rp = &s_rz[(yo + di) * 132 + xx * 2];
                        CONV_ROW(rp, w2[di], acc);
                    }
                    float vx = 0.9f * v[yo][j].x + acc.x;
                    float vy = 0.9f * v[yo][j].y + acc.y;
                    if (vx > 1.0f) { vx -= 1.0f; c0++; }
                    if (vy > 1.0f) { vy -= 1.0f; c1++; }
                    v[yo][j].x = vx; v[yo][j].y = vy;
                }
            }
            atomicAdd(&s_cnt[t * 32 + 2 * p],     c0);
            atomicAdd(&s_cnt[t * 32 + 2 * p + 1], c1);
            __syncthreads();
        }
        for (int i = tid; i < 1024; i += 256) {
            int t = i >> 5, c = i & 31;
            int val = s_cnt[i];
            if (val) atomicAdd(&g_fcnt[(t * 32 + b) * 96 + 64 + c], val);
        }
    }
}

// ---------------- k_logits ----------------
// grid: T*B = 1024 blocks, 128 threads
__global__ void k_logits(const float* __restrict__ head_w, const float* __restrict__ head_b,
                         const float* __restrict__ route_w, const float* __restrict__ route_b,
                         float* __restrict__ out) {
    int tb = blockIdx.x;
    int o = threadIdx.x;
    __shared__ float s_f[96];
    __shared__ float s_s[256];
    if (o < 96) {
        float scale = (o < 64) ? (1.f / 1024.f) : (1.f / 4096.f);
        s_f[o] = (float)g_fcnt[tb * 96 + o] * scale;
    }
    for (int k = o; k < 256; k += 128) s_s[k] = g_scores[tb * 256 + k];
    __syncthreads();
    float acc = head_b[o] + route_b[o];
    for (int c = 0; c < 96; c++)  acc += s_f[c] * head_w[c * 128 + o];
    for (int k = 0; k < 256; k++) acc += s_s[k] * route_w[k * 128 + o];
    out[OFF_LOGITS + (size_t)tb * 128 + o] = acc;
}

// ---------------- k_final: mean over T + stats ----------------
__global__ void k_final(float* __restrict__ out) {
    int bid = blockIdx.x, tid = threadIdx.x;
    if (bid < 32) {
        float acc = 0.f;
        for (int t = 0; t < 32; t++)
            acc += out[OFF_LOGITS + (size_t)(t * 32 + bid) * 128 + tid];
        out[bid * 128 + tid] = acc * (1.f / 32.f);
    } else {
        for (int k = tid; k < 256; k += 128)
            out[OFF_ROUTE + k] = (float)g_route[k] * (1.f / 1024.f);
        if (tid < 64)
            out[OFF_CHAN + tid] = (float)g_chan[tid] * (1.f / 1024.f);
        __shared__ int r0[128], r1[128];
        int c0 = 0, c1 = 0;
        for (int i = tid; i < T_ * B_ * 96; i += 128) {
            int c = i % 96;
            int vv = g_fcnt[i];
            if (c < 64) c0 += vv; else c1 += vv;
        }
        r0[tid] = c0; r1[tid] = c1;
        __syncthreads();
        for (int off = 64; off > 0; off >>= 1) {
            if (tid < off) { r0[tid] += r0[tid + off]; r1[tid] += r1[tid + off]; }
            __syncthreads();
        }
        if (tid == 0) {
            out[OFF_SR + 0] = (float)r0[0] * (1.f / 67108864.f);    // T*B*32*32*64
            out[OFF_SR + 1] = (float)r1[0] * (1.f / 134217728.f);   // T*B*64*64*32
            out[OFF_ACTIVE] = (float)g_active * (1.f / 33554432.f); // T*B*128*128*2
        }
    }
}

// ---------------- launch ----------------
extern "C" void kernel_launch(void* const* d_in, const int* in_sizes, int n_in,
                              void* d_out, int out_size) {
    const float* x_seq    = (const float*)d_in[0];
    const float* w_fovea  = (const float*)d_in[1];
    const float* w_periph = (const float*)d_in[2];
    const float* head_w   = (const float*)d_in[3];
    const float* head_b   = (const float*)d_in[4];
    const float* route_w  = (const float*)d_in[5];
    const float* route_b  = (const float*)d_in[6];
    float* out = (float*)d_out;

    k_init<<<384, 256>>>();
    k_pre<<<T_ * B_, 256>>>(x_seq, w_fovea);
    k_lif<<<768, 256>>>(x_seq, w_fovea, w_periph);
    k_logits<<<T_ * B_, 128>>>(head_w, head_b, route_w, route_b, out);
    k_final<<<33, 128>>>(out);
}

// round 8
// speedup vs baseline: 5.0566x; 1.1949x over previous
#include <cuda_runtime.h>
#include <math.h>

#define T_   32
#define B_   32
#define H_   128
#define W_   128

// output layout offsets (floats)
#define OFF_LOGITS 4096
#define OFF_SR     135168
#define OFF_ACTIVE 135170
#define OFF_ROUTE  135171
#define OFF_CHAN   135427

// ---------------- persistent device state ----------------
__device__ float g_scores[T_ * B_ * 256];
__device__ __align__(16) float g_gate[T_ * B_ * 64];   // float2-loaded
__device__ int   g_y0[T_ * B_], g_x0[T_ * B_];
__device__ int   g_fcnt[T_ * B_ * 96];     // spike counts per (t,b,channel)
__device__ int   g_route[256];
__device__ int   g_chan[64];
__device__ int   g_active;
__device__ __align__(16) float g_rz[T_ * B_ * 64 * 128];  // resized periph frames (32 MB)

// packed fp32x2 FMA (Blackwell FFMA2) — bit-exact IEEE fp32 per lane
__device__ __forceinline__ float2 ffma2(float a, float2 w, float2 c) {
#if __CUDA_ARCH__ >= 1000
    union { float2 f; unsigned long long u; } A, W, C, R;
    A.f = make_float2(a, a); W.f = w; C.f = c;
    asm("fma.rn.f32x2 %0, %1, %2, %3;" : "=l"(R.u) : "l"(A.u), "l"(W.u), "l"(C.u));
    return R.f;
#else
    return make_float2(fmaf(a, w.x, c.x), fmaf(a, w.y, c.y));
#endif
}

// 6 taps of one conv row (3 x-positions x 2 input channels), channel-pair packed.
#define CONV_ROW(rp, wrow, acc) do {                       \
    float2 _i0 = ((const float2*)(rp))[0];                 \
    float2 _i1 = ((const float2*)(rp))[1];                 \
    float2 _i2 = ((const float2*)(rp))[2];                 \
    acc = ffma2(_i0.x, (wrow)[0][0], acc);                 \
    acc = ffma2(_i0.y, (wrow)[0][1], acc);                 \
    acc = ffma2(_i1.x, (wrow)[1][0], acc);                 \
    acc = ffma2(_i1.y, (wrow)[1][1], acc);                 \
    acc = ffma2(_i2.x, (wrow)[2][0], acc);                 \
    acc = ffma2(_i2.y, (wrow)[2][1], acc);                 \
} while (0)

__device__ __forceinline__ float evmask(float v) { return (fabsf(v) > 0.5f) ? v : 0.f; }

// ---------------- init ----------------
__global__ void k_init() {
    int i = blockIdx.x * blockDim.x + threadIdx.x;
    int stride = gridDim.x * blockDim.x;
    for (int j = i; j < T_ * B_ * 96; j += stride) g_fcnt[j] = 0;
    if (i < 256) g_route[i] = 0;
    if (i < 64)  g_chan[i]  = 0;
    if (i == 0)  g_active   = 0;
}

// ---------------- k_prep ----------------
// blocks [0,1024): per (t,b) scores/argmax/route/active + fovea conv -> sal -> KWTA gate
// blocks [1024, 1024+8192): periph resize precompute -> g_rz (8 output rows per block)
__global__ void __launch_bounds__(256, 4)
k_prep(const float* __restrict__ x_seq, const float* __restrict__ w_fovea) {
    __shared__ __align__(16) float sb[6984];
    int bx = blockIdx.x, tid = threadIdx.x;

    if (bx < 1024) {
        int b = bx & 31, t = bx >> 5;
        int tb = t * 32 + b;
        const float* x = x_seq + (size_t)tb * 32768;

        float* s_sc  = sb;                                   // 256
        unsigned long long* s_key = (unsigned long long*)(sb + 256);  // 256 ull (8B-aligned)
        int*   s_acnt = (int*)(sb + 768);                    // 256
        float* s_win  = sb + 1024;                           // 34*68 = 2312 (16B-aligned)
        float* s_asum = sb + 3336;                           // 512
        float* s_sal  = sb + 3848;                           // 64
        float* s_thresh = sb + 3912;
        float* s_thr2   = sb + 3913;
        int*   s_y0p = (int*)(sb + 3914);
        int*   s_x0p = (int*)(sb + 3915);

        // ---- part 1: patch scores (same element order as scalar version) ----
        int py = tid >> 4, px = tid & 15;
        float sum = 0.f; int cnt = 0;
        for (int r = 0; r < 8; r++) {
            const float4* row = (const float4*)(x + ((py * 8 + r) * W_ + px * 8) * 2);
#pragma unroll
            for (int k4 = 0; k4 < 4; k4++) {
                float4 v4 = row[k4];
                float a;
                a = fabsf(v4.x); if (a > 0.5f) { cnt++; sum += a; }
                a = fabsf(v4.y); if (a > 0.5f) { cnt++; sum += a; }
                a = fabsf(v4.z); if (a > 0.5f) { cnt++; sum += a; }
                a = fabsf(v4.w); if (a > 0.5f) { cnt++; sum += a; }
            }
        }
        float sc = sum * (1.f / 128.f);
        s_sc[tid] = sc;
        g_scores[tb * 256 + tid] = sc;
        s_acnt[tid] = cnt;
        unsigned int fb = __float_as_uint(sc);   // sc >= 0 -> order-preserving
        s_key[tid] = (((unsigned long long)fb) << 32) | (unsigned long long)(0xFFFFFFFFu - (unsigned)tid);
        __syncthreads();

        // exact top-4 threshold (JAX top_k tie semantics)
        int cg = 0, ceq = 0;
        for (int j = 0; j < 256; j++) {
            float v = s_sc[j];
            cg  += (v > sc);
            ceq += (v == sc);
        }
        if (cg <= 3 && cg + ceq > 3) *s_thresh = sc;

        for (int off = 128; off > 0; off >>= 1) {
            __syncthreads();
            if (tid < off) {
                s_acnt[tid] += s_acnt[tid + off];
                if (s_key[tid + off] > s_key[tid]) s_key[tid] = s_key[tid + off];
            }
        }
        __syncthreads();

        if (sc >= *s_thresh) atomicAdd(&g_route[tid], 1);
        if (tid == 0) {
            atomicAdd(&g_active, s_acnt[0]);
            unsigned int low = (unsigned int)(s_key[0] & 0xFFFFFFFFull);
            int best = (int)(0xFFFFFFFFu - low);
            int cy = (best >> 4) * 8 + 4;
            int cx = (best & 15) * 8 + 4;
            int y0 = cy - 16; y0 = y0 < 0 ? 0 : (y0 > 96 ? 96 : y0);
            int x0 = cx - 16; x0 = x0 < 0 ? 0 : (x0 > 96 ? 96 : x0);
            *s_y0p = y0; *s_x0p = x0;
            g_y0[tb] = y0; g_x0[tb] = x0;
        }

        // ---- part 2: fovea window load (event-masked, zero-padded) ----
        for (int i = tid; i < 34 * 68; i += 256) s_win[i] = 0.f;
        __syncthreads();
        int y0 = *s_y0p, x0 = *s_x0p;       // x0,y0 even -> float4-aligned
        for (int i = tid; i < 512; i += 256) {
            int rr = i >> 4, c4 = i & 15;
            float4 xv = *(const float4*)&x[(size_t)(y0 + rr) * 256 + x0 * 2 + c4 * 4];
            float* dst = &s_win[(rr + 1) * 68 + c4 * 4 + 2];
            dst[0] = evmask(xv.x); dst[1] = evmask(xv.y);
            dst[2] = evmask(xv.z); dst[3] = evmask(xv.w);
        }
        __syncthreads();

        // ---- part 3: conv -> per-channel |ff| sums -> KWTA gate ----
        int p = tid & 31;           // channel pair
        int g = tid >> 5;           // row group (4 rows each)
        float2 w2[3][3][2];
#pragma unroll
        for (int di = 0; di < 3; di++)
#pragma unroll
            for (int dj = 0; dj < 3; dj++)
#pragma unroll
                for (int ci = 0; ci < 2; ci++)
                    w2[di][dj][ci] = *(const float2*)&w_fovea[((di * 3 + dj) * 2 + ci) * 64 + 2 * p];

        float2 asum = make_float2(0.f, 0.f);
        for (int rq = 0; rq < 4; rq++) {
            int row = g * 4 + rq;
#pragma unroll 4
            for (int j = 0; j < 32; j++) {
                float2 acc = make_float2(0.f, 0.f);
#pragma unroll
                for (int di = 0; di < 3; di++) {
                    const float* rp = &s_win[(row + di) * 68 + j * 2];
                    CONV_ROW(rp, w2[di], acc);
                }
                asum.x += fabsf(acc.x);
                asum.y += fabsf(acc.y);
            }
        }
        s_asum[g * 64 + 2 * p]     = asum.x;
        s_asum[g * 64 + 2 * p + 1] = asum.y;
        __syncthreads();
        if (tid < 64) {
            float s = 0.f;
#pragma unroll
            for (int gg = 0; gg < 8; gg++) s += s_asum[gg * 64 + tid];
            s_sal[tid] = s;
        }
        __syncthreads();
        if (tid < 64) {
            float vv = s_sal[tid];
            int cg2 = 0, ce2 = 0;
            for (int j = 0; j < 64; j++) {
                float u = s_sal[j];
                cg2 += (u > vv);
                ce2 += (u == vv);
            }
            if (cg2 <= 15 && cg2 + ce2 > 15) *s_thr2 = vv;
        }
        __syncthreads();
        if (tid < 64) {
            float gt = (s_sal[tid] >= *s_thr2) ? 1.f : 0.f;
            g_gate[tb * 64 + tid] = gt;
            if (gt > 0.f) atomicAdd(&g_chan[tid], 1);
        }
    } else {
        // ================= periph resize precompute: 8 output rows per block =================
        int rb = bx - 1024;
        int tb = rb >> 3;
        int oy0 = (rb & 7) * 8;
        int hr0 = 2 * oy0 - 1;              // global x-row of local h row 0 (18 rows)
        const float* x = x_seq + (size_t)tb * 32768;

        float* s_x = sb;                    // [18][260] zero-padded cols
        float* s_h = sb + 4680;             // [18][128]

        for (int i = tid; i < 4680; i += 256) s_x[i] = 0.f;
        __syncthreads();
        for (int i = tid; i < 18 * 64; i += 256) {      // 64 float4 per row
            int r = i >> 6, c4 = i & 63;
            int gr = hr0 + r;
            if (gr >= 0 && gr < 128) {
                float4 xv = *(const float4*)&x[(size_t)gr * 256 + c4 * 4];
                float* dst = &s_x[r * 260 + 2 + c4 * 4];
                dst[0] = evmask(xv.x); dst[1] = evmask(xv.y);
                dst[2] = evmask(xv.z); dst[3] = evmask(xv.w);
            }
        }
        __syncthreads();
        // horizontal resize (exact JAX antialias-linear weights; OOB taps weight 0)
        for (int i = tid; i < 2304; i += 256) {
            int r = i >> 7, rest = i & 127;
            int ox = rest >> 1, c = rest & 1;
            int kb; float w0, w1, wm, w3;
            if (ox == 0)       { kb = -1;  w0 = 0.f;       w1 = 3.f / 7.f; wm = 3.f / 7.f; w3 = 1.f / 7.f; }
            else if (ox == 63) { kb = 125; w0 = 1.f / 7.f; w1 = 3.f / 7.f; wm = 3.f / 7.f; w3 = 0.f; }
            else               { kb = 2 * ox - 1; w0 = 0.125f; w1 = 0.375f; wm = 0.375f; w3 = 0.125f; }
            const float* xr = &s_x[r * 260 + 2 + c];
            float vv = w0 * xr[kb * 2] + w1 * xr[(kb + 1) * 2]
                     + wm * xr[(kb + 2) * 2] + w3 * xr[(kb + 3) * 2];
            s_h[i] = vv;
        }
        __syncthreads();
        // vertical resize + store
        for (int i = tid; i < 1024; i += 256) {
            int lr = i >> 7, rest = i & 127;
            int oy = oy0 + lr;
            int jb; float w0, w1, wm, w3;
            if (oy == 0)       { jb = -1;  w0 = 0.f;       w1 = 3.f / 7.f; wm = 3.f / 7.f; w3 = 1.f / 7.f; }
            else if (oy == 63) { jb = 125; w0 = 1.f / 7.f; w1 = 3.f / 7.f; wm = 3.f / 7.f; w3 = 0.f; }
            else               { jb = 2 * oy - 1; w0 = 0.125f; w1 = 0.375f; wm = 0.375f; w3 = 0.125f; }
            int base = jb - hr0;
            float vv = w0 * s_h[base * 128 + rest]       + w1 * s_h[(base + 1) * 128 + rest]
                     + wm * s_h[(base + 2) * 128 + rest] + w3 * s_h[(base + 3) * 128 + rest];
            g_rz[(size_t)tb * 8192 + (size_t)oy * 128 + rest] = vv;
        }
    }
}

// ---------------- k_lif: all 32 timesteps in registers ----------------
// blocks [0,256): fovea   — b = bx>>3, row tile = bx&7 (4 rows)
// blocks [256,768): periph — b = (bx-256)>>4, row tile = (bx-256)&15 (4 output rows)
__global__ void __launch_bounds__(256, 2)
k_lif(const float* __restrict__ x_seq,
      const float* __restrict__ w_fovea,
      const float* __restrict__ w_periph) {
    __shared__ __align__(16) float sbuf[2464];
    int bx = blockIdx.x;
    int tid = threadIdx.x;

    if (bx < 256) {
        // ================= fovea: conv recompute + gate + LIF =================
        int b = bx >> 3, tile = bx & 7;
        float* s_in  = sbuf;                 // [6][68] zero-padded (row 272B)
        int*   s_cnt = (int*)(sbuf + 416);   // [32][64]

        for (int i = tid; i < 408;  i += 256) s_in[i] = 0.f;
        for (int i = tid; i < 2048; i += 256) s_cnt[i] = 0;

        int p  = tid & 31;         // channel pair
        int q  = (tid >> 5) & 3;   // row within tile
        int xh = tid >> 7;         // x half

        float2 w2[3][3][2];
#pragma unroll
        for (int di = 0; di < 3; di++)
#pragma unroll
            for (int dj = 0; dj < 3; dj++)
#pragma unroll
                for (int ci = 0; ci < 2; ci++)
                    w2[di][dj][ci] = *(const float2*)&w_fovea[((di * 3 + dj) * 2 + ci) * 64 + 2 * p];

        float2 v[16];
#pragma unroll
        for (int j = 0; j < 16; j++) v[j] = make_float2(0.f, 0.f);

        int r0 = tile * 4;
        __syncthreads();

        for (int t = 0; t < 32; t++) {
            int tb = t * 32 + b;
            int y0 = g_y0[tb], x0 = g_x0[tb];
            const float* x = x_seq + (size_t)tb * 32768;
            if (tid < 96) {
                int rr = tid >> 4, c4 = tid & 15;
                int lrow = r0 - 1 + rr;
                if (lrow >= 0 && lrow < 32) {
                    float4 xv = *(const float4*)&x[(size_t)(y0 + lrow) * 256 + x0 * 2 + c4 * 4];
                    float* dst = &s_in[rr * 68 + c4 * 4 + 2];
                    dst[0] = evmask(xv.x); dst[1] = evmask(xv.y);
                    dst[2] = evmask(xv.z); dst[3] = evmask(xv.w);
                }
            }
            float2 g2 = *(const float2*)&g_gate[tb * 64 + 2 * p];
            __syncthreads();

            int c0 = 0, c1 = 0;
#pragma unroll
            for (int j = 0; j < 16; j++) {
                int xx = xh * 16 + j;
                float2 acc = make_float2(0.f, 0.f);
#pragma unroll
                for (int di = 0; di < 3; di++) {
                    const float* rp = &s_in[(q + di) * 68 + xx * 2];
                    CONV_ROW(rp, w2[di], acc);
                }
                float vx = 0.9f * v[j].x + acc.x * g2.x;
                float vy = 0.9f * v[j].y + acc.y * g2.y;
                if (vx > 1.0f) { vx -= 1.0f; c0++; }
                if (vy > 1.0f) { vy -= 1.0f; c1++; }
                v[j].x = vx; v[j].y = vy;
            }
            atomicAdd(&s_cnt[t * 64 + 2 * p],     c0);
            atomicAdd(&s_cnt[t * 64 + 2 * p + 1], c1);
            __syncthreads();
        }
        for (int i = tid; i < 2048; i += 256) {
            int t = i >> 6, c = i & 63;
            int val = s_cnt[i];
            if (val) atomicAdd(&g_fcnt[(t * 32 + b) * 96 + c], val);
        }
    } else {
        // ================= periph: precomputed resize + conv + LIF =================
        int pbx = bx - 256;
        int b = pbx >> 4, tile = pbx & 15;        // output rows [4*tile, 4*tile+4)
        float* s_rz  = sbuf;                       // [6][132] zero-padded (row 528B)
        int*   s_cnt = (int*)(sbuf + 800);         // [32][32]

        for (int i = tid; i < 792;  i += 256) s_rz[i] = 0.f;
        for (int i = tid; i < 1024; i += 256) s_cnt[i] = 0;

        int p  = tid & 15;   // channel pair
        int xg = tid >> 4;   // x group: x in [4*xg, 4*xg+4)

        float2 w2[3][3][2];
#pragma unroll
        for (int di = 0; di < 3; di++)
#pragma unroll
            for (int dj = 0; dj < 3; dj++)
#pragma unroll
                for (int ci = 0; ci < 2; ci++)
                    w2[di][dj][ci] = *(const float2*)&w_periph[((di * 3 + dj) * 2 + ci) * 32 + 2 * p];

        float2 v[4][4];
#pragma unroll
        for (int yo = 0; yo < 4; yo++)
#pragma unroll
            for (int j = 0; j < 4; j++) v[yo][j] = make_float2(0.f, 0.f);

        __syncthreads();

        for (int t = 0; t < 32; t++) {
            const float* rzsrc = &g_rz[(size_t)(t * 32 + b) * 8192];
            for (int i = tid; i < 768; i += 256) {
                int lr = i >> 7, rest = i & 127;
                int row = 4 * tile - 1 + lr;
                if (row >= 0 && row < 64)
                    s_rz[lr * 132 + rest + 2] = rzsrc[(size_t)row * 128 + rest];
            }
            __syncthreads();

            int c0 = 0, c1 = 0;
#pragma unroll
            for (int yo = 0; yo < 4; yo++) {
#pragma unroll
                for (int j = 0; j < 4; j++) {
                    int xx = 4 * xg + j;
                    float2 acc = make_float2(0.f, 0.f);
#pragma unroll
                    for (int di = 0; di < 3; di++) {
                        const float* rp = &s_rz[(yo + di) * 132 + xx * 2];
                        CONV_ROW(rp, w2[di], acc);
                    }
                    float vx = 0.9f * v[yo][j].x + acc.x;
                    float vy = 0.9f * v[yo][j].y + acc.y;
                    if (vx > 1.0f) { vx -= 1.0f; c0++; }
                    if (vy > 1.0f) { vy -= 1.0f; c1++; }
                    v[yo][j].x = vx; v[yo][j].y = vy;
                }
            }
            atomicAdd(&s_cnt[t * 32 + 2 * p],     c0);
            atomicAdd(&s_cnt[t * 32 + 2 * p + 1], c1);
            __syncthreads();
        }
        for (int i = tid; i < 1024; i += 256) {
            int t = i >> 5, c = i & 31;
            int val = s_cnt[i];
            if (val) atomicAdd(&g_fcnt[(t * 32 + b) * 96 + 64 + c], val);
        }
    }
}

// ---------------- k_logits: 8 tb per block for route_w reuse ----------------
// grid: 128 blocks, 128 threads
__global__ void __launch_bounds__(128, 8)
k_logits(const float* __restrict__ head_w, const float* __restrict__ head_b,
         const float* __restrict__ route_w, const float* __restrict__ route_b,
         float* __restrict__ out) {
    int g = blockIdx.x;      // tb = g*8 + ib
    int o = threadIdx.x;
    __shared__ float s_f[8][96];
    __shared__ float s_s[8][256];
    for (int i = o; i < 8 * 96; i += 128) {
        int ib = i / 96, c = i % 96;
        float scale = (c < 64) ? (1.f / 1024.f) : (1.f / 4096.f);
        s_f[ib][c] = (float)g_fcnt[(g * 8 + ib) * 96 + c] * scale;
    }
    for (int i = o; i < 8 * 256; i += 128) {
        int ib = i >> 8, k = i & 255;
        s_s[ib][k] = g_scores[(g * 8 + ib) * 256 + k];
    }
    __syncthreads();
    float base = head_b[o] + route_b[o];
    float acc[8];
#pragma unroll
    for (int ib = 0; ib < 8; ib++) acc[ib] = base;
    for (int c = 0; c < 96; c++) {
        float w = head_w[c * 128 + o];
#pragma unroll
        for (int ib = 0; ib < 8; ib++) acc[ib] = fmaf(s_f[ib][c], w, acc[ib]);
    }
    for (int k = 0; k < 256; k++) {
        float w = route_w[k * 128 + o];
#pragma unroll
        for (int ib = 0; ib < 8; ib++) acc[ib] = fmaf(s_s[ib][k], w, acc[ib]);
    }
#pragma unroll
    for (int ib = 0; ib < 8; ib++)
        out[OFF_LOGITS + (size_t)(g * 8 + ib) * 128 + o] = acc[ib];
}

// ---------------- k_final: mean over T + stats ----------------
__global__ void k_final(float* __restrict__ out) {
    int bid = blockIdx.x, tid = threadIdx.x;
    if (bid < 32) {
        float acc = 0.f;
        for (int t = 0; t < 32; t++)
            acc += out[OFF_LOGITS + (size_t)(t * 32 + bid) * 128 + tid];
        out[bid * 128 + tid] = acc * (1.f / 32.f);
    } else {
        for (int k = tid; k < 256; k += 128)
            out[OFF_ROUTE + k] = (float)g_route[k] * (1.f / 1024.f);
        if (tid < 64)
            out[OFF_CHAN + tid] = (float)g_chan[tid] * (1.f / 1024.f);
        __shared__ int r0[128], r1[128];
        int c0 = 0, c1 = 0;
        for (int i = tid; i < T_ * B_ * 96; i += 128) {
            int c = i % 96;
            int vv = g_fcnt[i];
            if (c < 64) c0 += vv; else c1 += vv;
        }
        r0[tid] = c0; r1[tid] = c1;
        __syncthreads();
        for (int off = 64; off > 0; off >>= 1) {
            if (tid < off) { r0[tid] += r0[tid + off]; r1[tid] += r1[tid + off]; }
            __syncthreads();
        }
        if (tid == 0) {
            out[OFF_SR + 0] = (float)r0[0] * (1.f / 67108864.f);    // T*B*32*32*64
            out[OFF_SR + 1] = (float)r1[0] * (1.f / 134217728.f);   // T*B*64*64*32
            out[OFF_ACTIVE] = (float)g_active * (1.f / 33554432.f); // T*B*128*128*2
        }
    }
}

// ---------------- launch ----------------
extern "C" void kernel_launch(void* const* d_in, const int* in_sizes, int n_in,
                              void* d_out, int out_size) {
    const float* x_seq    = (const float*)d_in[0];
    const float* w_fovea  = (const float*)d_in[1];
    const float* w_periph = (const float*)d_in[2];
    const float* head_w   = (const float*)d_in[3];
    const float* head_b   = (const float*)d_in[4];
    const float* route_w  = (const float*)d_in[5];
    const float* route_b  = (const float*)d_in[6];
    float* out = (float*)d_out;

    k_init<<<384, 256>>>();
    k_prep<<<1024 + 8192, 256>>>(x_seq, w_fovea);
    k_lif<<<768, 256>>>(x_seq, w_fovea, w_periph);
    k_logits<<<128, 128>>>(head_w, head_b, route_w, route_b, out);
    k_final<<<33, 128>>>(out);
}

// round 9
// speedup vs baseline: 5.1792x; 1.0242x over previous
#include <cuda_runtime.h>
#include <math.h>

#define T_   32
#define B_   32
#define H_   128
#define W_   128

// output layout offsets (floats)
#define OFF_LOGITS 4096
#define OFF_SR     135168
#define OFF_ACTIVE 135170
#define OFF_ROUTE  135171
#define OFF_CHAN   135427

// ---------------- persistent device state ----------------
__device__ float g_scores[T_ * B_ * 256];
__device__ __align__(16) float g_gate[T_ * B_ * 64];   // float2-loaded
__device__ int   g_y0[T_ * B_], g_x0[T_ * B_];
__device__ int   g_fcnt[T_ * B_ * 96];     // spike counts per (t,b,channel)
__device__ int   g_route[256];
__device__ int   g_chan[64];
__device__ int   g_active;
__device__ __align__(16) float g_rz[T_ * B_ * 64 * 128];  // resized periph frames (32 MB)

// packed fp32x2 FMA (Blackwell FFMA2) — bit-exact IEEE fp32 per lane
__device__ __forceinline__ float2 ffma2(float a, float2 w, float2 c) {
#if __CUDA_ARCH__ >= 1000
    union { float2 f; unsigned long long u; } A, W, C, R;
    A.f = make_float2(a, a); W.f = w; C.f = c;
    asm("fma.rn.f32x2 %0, %1, %2, %3;" : "=l"(R.u) : "l"(A.u), "l"(W.u), "l"(C.u));
    return R.f;
#else
    return make_float2(fmaf(a, w.x, c.x), fmaf(a, w.y, c.y));
#endif
}

// 6 taps of one conv row (3 x-positions x 2 input channels), channel-pair packed.
#define CONV_ROW(rp, wrow, acc) do {                       \
    float2 _i0 = ((const float2*)(rp))[0];                 \
    float2 _i1 = ((const float2*)(rp))[1];                 \
    float2 _i2 = ((const float2*)(rp))[2];                 \
    acc = ffma2(_i0.x, (wrow)[0][0], acc);                 \
    acc = ffma2(_i0.y, (wrow)[0][1], acc);                 \
    acc = ffma2(_i1.x, (wrow)[1][0], acc);                 \
    acc = ffma2(_i1.y, (wrow)[1][1], acc);                 \
    acc = ffma2(_i2.x, (wrow)[2][0], acc);                 \
    acc = ffma2(_i2.y, (wrow)[2][1], acc);                 \
} while (0)

__device__ __forceinline__ float evmask(float v) { return (fabsf(v) > 0.5f) ? v : 0.f; }

// ---------------- init ----------------
__global__ void k_init() {
    int i = blockIdx.x * blockDim.x + threadIdx.x;
    int stride = gridDim.x * blockDim.x;
    for (int j = i; j < T_ * B_ * 96; j += stride) g_fcnt[j] = 0;
    if (i < 256) g_route[i] = 0;
    if (i < 64)  g_chan[i]  = 0;
    if (i == 0)  g_active   = 0;
}

// ---------------- k_prep ----------------
// blocks [0,1024): per (t,b) scores/argmax/route/active + fovea conv -> sal -> KWTA gate
// blocks [1024, 1024+8192): periph resize precompute -> g_rz (8 output rows per block)
__global__ void __launch_bounds__(256, 4)
k_prep(const float* __restrict__ x_seq, const float* __restrict__ w_fovea) {
    __shared__ __align__(16) float sb[6984];
    int bx = blockIdx.x, tid = threadIdx.x;

    if (bx < 1024) {
        int b = bx & 31, t = bx >> 5;
        int tb = t * 32 + b;
        const float* x = x_seq + (size_t)tb * 32768;

        float* s_sc  = sb;                                   // 256
        unsigned long long* s_key = (unsigned long long*)(sb + 256);  // 256 ull
        int*   s_acnt = (int*)(sb + 768);                    // 256
        float* s_win  = sb + 1024;                           // 34*68 = 2312
        float* s_asum = sb + 3336;                           // 512
        float* s_sal  = sb + 3848;                           // 64
        float* s_thresh = sb + 3912;
        float* s_thr2   = sb + 3913;
        int*   s_y0p = (int*)(sb + 3914);
        int*   s_x0p = (int*)(sb + 3915);

        // ---- part 1: patch scores (same element order as scalar version) ----
        int py = tid >> 4, px = tid & 15;
        float sum = 0.f; int cnt = 0;
        for (int r = 0; r < 8; r++) {
            const float4* row = (const float4*)(x + ((py * 8 + r) * W_ + px * 8) * 2);
#pragma unroll
            for (int k4 = 0; k4 < 4; k4++) {
                float4 v4 = row[k4];
                float a;
                a = fabsf(v4.x); if (a > 0.5f) { cnt++; sum += a; }
                a = fabsf(v4.y); if (a > 0.5f) { cnt++; sum += a; }
                a = fabsf(v4.z); if (a > 0.5f) { cnt++; sum += a; }
                a = fabsf(v4.w); if (a > 0.5f) { cnt++; sum += a; }
            }
        }
        float sc = sum * (1.f / 128.f);
        s_sc[tid] = sc;
        g_scores[tb * 256 + tid] = sc;
        s_acnt[tid] = cnt;
        unsigned int fb = __float_as_uint(sc);   // sc >= 0 -> order-preserving
        s_key[tid] = (((unsigned long long)fb) << 32) | (unsigned long long)(0xFFFFFFFFu - (unsigned)tid);
        __syncthreads();

        // exact top-4 threshold (JAX top_k tie semantics)
        int cg = 0, ceq = 0;
        for (int j = 0; j < 256; j++) {
            float v = s_sc[j];
            cg  += (v > sc);
            ceq += (v == sc);
        }
        if (cg <= 3 && cg + ceq > 3) *s_thresh = sc;

        for (int off = 128; off > 0; off >>= 1) {
            __syncthreads();
            if (tid < off) {
                s_acnt[tid] += s_acnt[tid + off];
                if (s_key[tid + off] > s_key[tid]) s_key[tid] = s_key[tid + off];
            }
        }
        __syncthreads();

        if (sc >= *s_thresh) atomicAdd(&g_route[tid], 1);
        if (tid == 0) {
            atomicAdd(&g_active, s_acnt[0]);
            unsigned int low = (unsigned int)(s_key[0] & 0xFFFFFFFFull);
            int best = (int)(0xFFFFFFFFu - low);
            int cy = (best >> 4) * 8 + 4;
            int cx = (best & 15) * 8 + 4;
            int y0 = cy - 16; y0 = y0 < 0 ? 0 : (y0 > 96 ? 96 : y0);
            int x0 = cx - 16; x0 = x0 < 0 ? 0 : (x0 > 96 ? 96 : x0);
            *s_y0p = y0; *s_x0p = x0;
            g_y0[tb] = y0; g_x0[tb] = x0;
        }

        // ---- part 2: fovea window load (event-masked, zero-padded) ----
        for (int i = tid; i < 34 * 68; i += 256) s_win[i] = 0.f;
        __syncthreads();
        int y0 = *s_y0p, x0 = *s_x0p;       // x0,y0 even -> float4-aligned
        for (int i = tid; i < 512; i += 256) {
            int rr = i >> 4, c4 = i & 15;
            float4 xv = *(const float4*)&x[(size_t)(y0 + rr) * 256 + x0 * 2 + c4 * 4];
            float* dst = &s_win[(rr + 1) * 68 + c4 * 4 + 2];
            dst[0] = evmask(xv.x); dst[1] = evmask(xv.y);
            dst[2] = evmask(xv.z); dst[3] = evmask(xv.w);
        }
        __syncthreads();

        // ---- part 3: conv -> per-channel |ff| sums -> KWTA gate ----
        int p = tid & 31;           // channel pair
        int g = tid >> 5;           // row group (4 rows each)
        float2 w2[3][3][2];
#pragma unroll
        for (int di = 0; di < 3; di++)
#pragma unroll
            for (int dj = 0; dj < 3; dj++)
#pragma unroll
                for (int ci = 0; ci < 2; ci++)
                    w2[di][dj][ci] = *(const float2*)&w_fovea[((di * 3 + dj) * 2 + ci) * 64 + 2 * p];

        float2 asum = make_float2(0.f, 0.f);
        for (int rq = 0; rq < 4; rq++) {
            int row = g * 4 + rq;
#pragma unroll 4
            for (int j = 0; j < 32; j++) {
                float2 acc = make_float2(0.f, 0.f);
#pragma unroll
                for (int di = 0; di < 3; di++) {
                    const float* rp = &s_win[(row + di) * 68 + j * 2];
                    CONV_ROW(rp, w2[di], acc);
                }
                asum.x += fabsf(acc.x);
                asum.y += fabsf(acc.y);
            }
        }
        s_asum[g * 64 + 2 * p]     = asum.x;
        s_asum[g * 64 + 2 * p + 1] = asum.y;
        __syncthreads();
        if (tid < 64) {
            float s = 0.f;
#pragma unroll
            for (int gg = 0; gg < 8; gg++) s += s_asum[gg * 64 + tid];
            s_sal[tid] = s;
        }
        __syncthreads();
        if (tid < 64) {
            float vv = s_sal[tid];
            int cg2 = 0, ce2 = 0;
            for (int j = 0; j < 64; j++) {
                float u = s_sal[j];
                cg2 += (u > vv);
                ce2 += (u == vv);
            }
            if (cg2 <= 15 && cg2 + ce2 > 15) *s_thr2 = vv;
        }
        __syncthreads();
        if (tid < 64) {
            float gt = (s_sal[tid] >= *s_thr2) ? 1.f : 0.f;
            g_gate[tb * 64 + tid] = gt;
            if (gt > 0.f) atomicAdd(&g_chan[tid], 1);
        }
    } else {
        // ================= periph resize precompute: 8 output rows per block =================
        int rb = bx - 1024;
        int tb = rb >> 3;
        int oy0 = (rb & 7) * 8;
        int hr0 = 2 * oy0 - 1;              // global x-row of local h row 0 (18 rows)
        const float* x = x_seq + (size_t)tb * 32768;

        float* s_x = sb;                    // [18][260] zero-padded cols
        float* s_h = sb + 4680;             // [18][128]

        for (int i = tid; i < 4680; i += 256) s_x[i] = 0.f;
        __syncthreads();
        for (int i = tid; i < 18 * 64; i += 256) {      // 64 float4 per row
            int r = i >> 6, c4 = i & 63;
            int gr = hr0 + r;
            if (gr >= 0 && gr < 128) {
                float4 xv = *(const float4*)&x[(size_t)gr * 256 + c4 * 4];
                float* dst = &s_x[r * 260 + 2 + c4 * 4];
                dst[0] = evmask(xv.x); dst[1] = evmask(xv.y);
                dst[2] = evmask(xv.z); dst[3] = evmask(xv.w);
            }
        }
        __syncthreads();
        // horizontal resize (exact JAX antialias-linear weights; OOB taps weight 0)
        for (int i = tid; i < 2304; i += 256) {
            int r = i >> 7, rest = i & 127;
            int ox = rest >> 1, c = rest & 1;
            int kb; float w0, w1, wm, w3;
            if (ox == 0)       { kb = -1;  w0 = 0.f;       w1 = 3.f / 7.f; wm = 3.f / 7.f; w3 = 1.f / 7.f; }
            else if (ox == 63) { kb = 125; w0 = 1.f / 7.f; w1 = 3.f / 7.f; wm = 3.f / 7.f; w3 = 0.f; }
            else               { kb = 2 * ox - 1; w0 = 0.125f; w1 = 0.375f; wm = 0.375f; w3 = 0.125f; }
            const float* xr = &s_x[r * 260 + 2 + c];
            float vv = w0 * xr[kb * 2] + w1 * xr[(kb + 1) * 2]
                     + wm * xr[(kb + 2) * 2] + w3 * xr[(kb + 3) * 2];
            s_h[i] = vv;
        }
        __syncthreads();
        // vertical resize + store
        for (int i = tid; i < 1024; i += 256) {
            int lr = i >> 7, rest = i & 127;
            int oy = oy0 + lr;
            int jb; float w0, w1, wm, w3;
            if (oy == 0)       { jb = -1;  w0 = 0.f;       w1 = 3.f / 7.f; wm = 3.f / 7.f; w3 = 1.f / 7.f; }
            else if (oy == 63) { jb = 125; w0 = 1.f / 7.f; w1 = 3.f / 7.f; wm = 3.f / 7.f; w3 = 0.f; }
            else               { jb = 2 * oy - 1; w0 = 0.125f; w1 = 0.375f; wm = 0.375f; w3 = 0.125f; }
            int base = jb - hr0;
            float vv = w0 * s_h[base * 128 + rest]       + w1 * s_h[(base + 1) * 128 + rest]
                     + wm * s_h[(base + 2) * 128 + rest] + w3 * s_h[(base + 3) * 128 + rest];
            g_rz[(size_t)tb * 8192 + (size_t)oy * 128 + rest] = vv;
        }
    }
}

// ---------------- k_lif: all 32 timesteps in registers ----------------
// blocks [0,512): fovea   — b = bx>>4, 2-row tile = bx&15
// blocks [512,1536): periph — b = (bx-512)>>5, 2-row tile = (bx-512)&31
__global__ void __launch_bounds__(256, 4)
k_lif(const float* __restrict__ x_seq,
      const float* __restrict__ w_fovea,
      const float* __restrict__ w_periph) {
    __shared__ __align__(16) float sbuf[2336];
    int bx = blockIdx.x;
    int tid = threadIdx.x;

    if (bx < 512) {
        // ================= fovea: conv recompute + gate + LIF (2 rows/block) ==========
        int b = bx >> 4, tile = bx & 15;
        float* s_in  = sbuf;                 // [4][68] zero-padded (row 272B)
        int*   s_cnt = (int*)(sbuf + 288);   // [32][64]

        for (int i = tid; i < 272;  i += 256) s_in[i] = 0.f;
        for (int i = tid; i < 2048; i += 256) s_cnt[i] = 0;

        int p  = tid & 31;         // channel pair
        int q  = (tid >> 5) & 1;   // row within tile
        int xq = tid >> 6;         // x quarter (0..3): 8 positions each

        float2 w2[3][3][2];
#pragma unroll
        for (int di = 0; di < 3; di++)
#pragma unroll
            for (int dj = 0; dj < 3; dj++)
#pragma unroll
                for (int ci = 0; ci < 2; ci++)
                    w2[di][dj][ci] = *(const float2*)&w_fovea[((di * 3 + dj) * 2 + ci) * 64 + 2 * p];

        float2 v[8];
#pragma unroll
        for (int j = 0; j < 8; j++) v[j] = make_float2(0.f, 0.f);

        int r0 = tile * 2;
        __syncthreads();

        for (int t = 0; t < 32; t++) {
            int tb = t * 32 + b;
            int y0 = g_y0[tb], x0 = g_x0[tb];
            const float* x = x_seq + (size_t)tb * 32768;
            if (tid < 64) {
                int rr = tid >> 4, c4 = tid & 15;
                int lrow = r0 - 1 + rr;
                if (lrow >= 0 && lrow < 32) {
                    float4 xv = *(const float4*)&x[(size_t)(y0 + lrow) * 256 + x0 * 2 + c4 * 4];
                    float* dst = &s_in[rr * 68 + c4 * 4 + 2];
                    dst[0] = evmask(xv.x); dst[1] = evmask(xv.y);
                    dst[2] = evmask(xv.z); dst[3] = evmask(xv.w);
                }
            }
            float2 g2 = *(const float2*)&g_gate[tb * 64 + 2 * p];
            __syncthreads();

            int c0 = 0, c1 = 0;
#pragma unroll
            for (int j = 0; j < 8; j++) {
                int xx = xq * 8 + j;
                float2 acc = make_float2(0.f, 0.f);
#pragma unroll
                for (int di = 0; di < 3; di++) {
                    const float* rp = &s_in[(q + di) * 68 + xx * 2];
                    CONV_ROW(rp, w2[di], acc);
                }
                float vx = 0.9f * v[j].x + acc.x * g2.x;
                float vy = 0.9f * v[j].y + acc.y * g2.y;
                if (vx > 1.0f) { vx -= 1.0f; c0++; }
                if (vy > 1.0f) { vy -= 1.0f; c1++; }
                v[j].x = vx; v[j].y = vy;
            }
            atomicAdd(&s_cnt[t * 64 + 2 * p],     c0);
            atomicAdd(&s_cnt[t * 64 + 2 * p + 1], c1);
            __syncthreads();
        }
        for (int i = tid; i < 2048; i += 256) {
            int t = i >> 6, c = i & 63;
            int val = s_cnt[i];
            if (val) atomicAdd(&g_fcnt[(t * 32 + b) * 96 + c], val);
        }
    } else {
        // ================= periph: precomputed resize + conv + LIF (2 rows/block) =====
        int pbx = bx - 512;
        int b = pbx >> 5, tile = pbx & 31;        // output rows [2*tile, 2*tile+2)
        float* s_rz  = sbuf;                       // [4][132] zero-padded (row 528B)
        int*   s_cnt = (int*)(sbuf + 544);         // [32][32]

        for (int i = tid; i < 528;  i += 256) s_rz[i] = 0.f;
        for (int i = tid; i < 1024; i += 256) s_cnt[i] = 0;

        int p  = tid & 15;   // channel pair
        int xg = tid >> 4;   // x group (0..15): 4 positions each

        float2 w2[3][3][2];
#pragma unroll
        for (int di = 0; di < 3; di++)
#pragma unroll
            for (int dj = 0; dj < 3; dj++)
#pragma unroll
                for (int ci = 0; ci < 2; ci++)
                    w2[di][dj][ci] = *(const float2*)&w_periph[((di * 3 + dj) * 2 + ci) * 32 + 2 * p];

        float2 v[2][4];
#pragma unroll
        for (int yo = 0; yo < 2; yo++)
#pragma unroll
            for (int j = 0; j < 4; j++) v[yo][j] = make_float2(0.f, 0.f);

        __syncthreads();

        for (int t = 0; t < 32; t++) {
            const float* rzsrc = &g_rz[(size_t)(t * 32 + b) * 8192];
            for (int i = tid; i < 512; i += 256) {
                int lr = i >> 7, rest = i & 127;
                int row = 2 * tile - 1 + lr;
                if (row >= 0 && row < 64)
                    s_rz[lr * 132 + rest + 2] = rzsrc[(size_t)row * 128 + rest];
            }
            __syncthreads();

            int c0 = 0, c1 = 0;
#pragma unroll
            for (int yo = 0; yo < 2; yo++) {
#pragma unroll
                for (int j = 0; j < 4; j++) {
                    int xx = 4 * xg + j;
                    float2 acc = make_float2(0.f, 0.f);
#pragma unroll
                    for (int di = 0; di < 3; di++) {
                        const float* rp = &s_rz[(yo + di) * 132 + xx * 2];
                        CONV_ROW(rp, w2[di], acc);
                    }
                    float vx = 0.9f * v[yo][j].x + acc.x;
                    float vy = 0.9f * v[yo][j].y + acc.y;
                    if (vx > 1.0f) { vx -= 1.0f; c0++; }
                    if (vy > 1.0f) { vy -= 1.0f; c1++; }
                    v[yo][j].x = vx; v[yo][j].y = vy;
                }
            }
            atomicAdd(&s_cnt[t * 32 + 2 * p],     c0);
            atomicAdd(&s_cnt[t * 32 + 2 * p + 1], c1);
            __syncthreads();
        }
        for (int i = tid; i < 1024; i += 256) {
            int t = i >> 5, c = i & 31;
            int val = s_cnt[i];
            if (val) atomicAdd(&g_fcnt[(t * 32 + b) * 96 + 64 + c], val);
        }
    }
}

// ---------------- k_logits: 4 tb per block, 256 blocks ----------------
__global__ void __launch_bounds__(128, 8)
k_logits(const float* __restrict__ head_w, const float* __restrict__ head_b,
         const float* __restrict__ route_w, const float* __restrict__ route_b,
         float* __restrict__ out) {
    int g = blockIdx.x;      // tb = g*4 + ib
    int o = threadIdx.x;
    __shared__ float s_f[4][96];
    __shared__ float s_s[4][256];
    for (int i = o; i < 4 * 96; i += 128) {
        int ib = i / 96, c = i % 96;
        float scale = (c < 64) ? (1.f / 1024.f) : (1.f / 4096.f);
        s_f[ib][c] = (float)g_fcnt[(g * 4 + ib) * 96 + c] * scale;
    }
    for (int i = o; i < 4 * 256; i += 128) {
        int ib = i >> 8, k = i & 255;
        s_s[ib][k] = g_scores[(g * 4 + ib) * 256 + k];
    }
    __syncthreads();
    float base = head_b[o] + route_b[o];
    float acc[4];
#pragma unroll
    for (int ib = 0; ib < 4; ib++) acc[ib] = base;
    for (int c = 0; c < 96; c++) {
        float w = head_w[c * 128 + o];
#pragma unroll
        for (int ib = 0; ib < 4; ib++) acc[ib] = fmaf(s_f[ib][c], w, acc[ib]);
    }
    for (int k = 0; k < 256; k++) {
        float w = route_w[k * 128 + o];
#pragma unroll
        for (int ib = 0; ib < 4; ib++) acc[ib] = fmaf(s_s[ib][k], w, acc[ib]);
    }
#pragma unroll
    for (int ib = 0; ib < 4; ib++)
        out[OFF_LOGITS + (size_t)(g * 4 + ib) * 128 + o] = acc[ib];
}

// ---------------- k_final: mean over T + stats ----------------
__global__ void k_final(float* __restrict__ out) {
    int bid = blockIdx.x, tid = threadIdx.x;
    if (bid < 32) {
        float acc = 0.f;
        for (int t = 0; t < 32; t++)
            acc += out[OFF_LOGITS + (size_t)(t * 32 + bid) * 128 + tid];
        out[bid * 128 + tid] = acc * (1.f / 32.f);
    } else {
        for (int k = tid; k < 256; k += 128)
            out[OFF_ROUTE + k] = (float)g_route[k] * (1.f / 1024.f);
        if (tid < 64)
            out[OFF_CHAN + tid] = (float)g_chan[tid] * (1.f / 1024.f);
        __shared__ int r0[128], r1[128];
        int c0 = 0, c1 = 0;
        for (int i = tid; i < T_ * B_ * 96; i += 128) {
            int c = i % 96;
            int vv = g_fcnt[i];
            if (c < 64) c0 += vv; else c1 += vv;
        }
        r0[tid] = c0; r1[tid] = c1;
        __syncthreads();
        for (int off = 64; off > 0; off >>= 1) {
            if (tid < off) { r0[tid] += r0[tid + off]; r1[tid] += r1[tid + off]; }
            __syncthreads();
        }
        if (tid == 0) {
            out[OFF_SR + 0] = (float)r0[0] * (1.f / 67108864.f);    // T*B*32*32*64
            out[OFF_SR + 1] = (float)r1[0] * (1.f / 134217728.f);   // T*B*64*64*32
            out[OFF_ACTIVE] = (float)g_active * (1.f / 33554432.f); // T*B*128*128*2
        }
    }
}

// ---------------- launch ----------------
extern "C" void kernel_launch(void* const* d_in, const int* in_sizes, int n_in,
                              void* d_out, int out_size) {
    const float* x_seq    = (const float*)d_in[0];
    const float* w_fovea  = (const float*)d_in[1];
    const float* w_periph = (const float*)d_in[2];
    const float* head_w   = (const float*)d_in[3];
    const float* head_b   = (const float*)d_in[4];
    const float* route_w  = (const float*)d_in[5];
    const float* route_b  = (const float*)d_in[6];
    float* out = (float*)d_out;

    k_init<<<384, 256>>>();
    k_prep<<<1024 + 8192, 256>>>(x_seq, w_fovea);
    k_lif<<<1536, 256>>>(x_seq, w_fovea, w_periph);
    k_logits<<<256, 128>>>(head_w, head_b, route_w, route_b, out);
    k_final<<<33, 128>>>(out);
}